// round 16
// baseline (speedup 1.0000x reference)
#include <cuda_runtime.h>
#include <cuda_bf16.h>
#include <math.h>

// z is (Kn=4, M=128, D=64, T=256)
#define Tn    256
#define NMID  254
#define ND    64
#define BW    6            // half-bandwidth 5 + diag (tau=0.5: c=6 entries ~5e-32)
#define BWP   8            // padded band stride (2x float4)
#define NPAD  264
#define NSTEP 258          // 43*6
#define JUMPJ 246          // 41*6: resume point after Toeplitz skip
#define EPSv  1e-5f

#define RSTRIDE 264        // smem row stride in floats: 8 pad + 256
#define NSTAGE  4
#define RPG     2          // rows per group per stage
#define RPS     (RPG * 4)  // 8 rows per stage

// dynamic smem layout (floats)
#define SBUF_F   (NSTAGE * RPS * RSTRIDE)          // 8448
#define LS_OFF   SBUF_F
#define LS_F     (NMID * BWP)                      // 2032
#define A0_OFF   (LS_OFF + LS_F)
#define A1_OFF   (A0_OFF + NMID)
#define SB_OFF   (A1_OFF + NMID)
#define SB_F     (NPAD * BW)                       // 1584
#define STC_OFF  (SB_OFF + SB_F)
#define GCS_OFF  (STC_OFF + 8)
#define SMEM_F   (GCS_OFF + 8)
#define SMEM_BYTES (SMEM_F * 4)                    // ~50.4 KB

#define NBLOCKS 444        // 3 * 148: exact round-robin balance on GB300

__device__ float g_pld[ND];
__device__ int   g_cnt = 0;

__global__ __launch_bounds__(256, 4) void fused_kernel(const float* __restrict__ z,
                                                       const float* __restrict__ sldj,
                                                       const float* __restrict__ log_tau,
                                                       float* __restrict__ out,
                                                       int osize) {
    extern __shared__ float smem[];
    float* sbuf = smem;
    float* Ls   = smem + LS_OFF;
    float* A0s  = smem + A0_OFF;
    float* A1s  = smem + A1_OFF;
    float* Sb   = smem + SB_OFF;     // [NPAD][BW] flattened
    float* stc  = smem + STC_OFF;
    float* gcs  = smem + GCS_OFF;

    const int bid = blockIdx.x;
    const int tid = threadIdx.x;
    const int tg = tid & 63;
    const int rs = tid >> 6;               // pipeline group 0..3
    const int t0 = tg << 2;

    // block -> (d, chunk): 60 d's with 7 chunks (80x4, 64x3 rows),
    //                      4 d's with 6 chunks (88x4, 80x2 rows)
    int d, chunk, niter, kbase;
    if (bid < 420) {
        d = bid / 7;
        chunk = bid - d * 7;
        if (chunk < 4) { niter = 10; kbase = chunk * 80; }
        else           { niter = 8;  kbase = 320 + (chunk - 4) * 64; }
    } else {
        int idx = bid - 420;
        d = 60 + idx / 6;
        chunk = idx - (idx / 6) * 6;
        if (chunk < 4) { niter = 11; kbase = chunk * 88; }
        else           { niter = 10; kbase = 352 + (chunk - 4) * 80; }
    }

    // -------- Phase 0: fire z prefetch FIRST (independent of band build) ----
    const int km0 = kbase + rs * (niter * RPG);             // group's first row
    const float* __restrict__ zbase = z + (size_t)(km0 * ND + d) * Tn + t0;
    float* __restrict__ obase = out + (size_t)(km0 * ND + d) * Tn + t0;
    const size_t rowpitch = (size_t)ND * Tn;
    const size_t iterstep = (size_t)RPG * rowpitch;         // 2 km-rows

    unsigned sdst_base;
    {
        void* p = (void*)&sbuf[0];
        sdst_base = (unsigned)__cvta_generic_to_shared(p);
    }
    const unsigned grp_off = (rs * RPG) * RSTRIDE + 8 + t0;
    const unsigned stage_bytes = RPS * RSTRIDE * 4u;

#pragma unroll
    for (int p = 0; p < 3; ++p) {
#pragma unroll
        for (int r = 0; r < RPG; ++r) {
            unsigned dst = sdst_base + p * stage_bytes + (grp_off + r * RSTRIDE) * 4u;
            const float* src = zbase + (size_t)p * iterstep + (size_t)r * rowpitch;
            asm volatile("cp.async.cg.shared.global [%0], [%1], 16;\n" :: "r"(dst), "l"(src));
        }
        asm volatile("cp.async.commit_group;\n" ::: "memory");
    }

    // ---------------- Phase A: band build (all 256 threads) ----------------
    const float tau = __expf(log_tau[d]);
    const float h = 1.0f / (2.0f * tau * tau);
    const float r255 = __expf(-h * 255.0f * 255.0f);
    const float idet = 1.0f / (1.0f - r255 * r255);

    if (tid < BW) gcs[tid] = __expf(-h * (float)(tid * tid));
    // zero front pads of all 32 row buffers (one float per thread)
    sbuf[(tid >> 3) * RSTRIDE + (tid & 7)] = 0.0f;
    // zero first 6 Ls band rows (entries c > i never written by recursion but
    // read by the unconditional tap loader; smem is not zero-initialized)
    if (tid < 6 * BWP) Ls[tid] = 0.0f;
    __syncthreads();

    for (int i = tid; i < NPAD; i += 256) {
        if (i < NMID) {
            float k0c[6], k1c[6];
#pragma unroll
            for (int c = 0; c < 6; ++c) {
                int ip = i - c;
                float x0 = (float)(ip + 1);
                float x1 = (float)(254 - ip);
                k0c[c] = __expf(-h * x0 * x0);
                k1c[c] = __expf(-h * x1 * x1);
            }
            float a0 = idet * (k0c[0] - r255 * k1c[0]);
            float a1 = idet * (k1c[0] - r255 * k0c[0]);
            A0s[i] = a0; A1s[i] = a1;
#pragma unroll
            for (int c = 0; c < 6; ++c) {
                float v = 0.0f;
                if (c <= i) {
                    v = gcs[c] - a0 * k0c[c] - a1 * k1c[c];
                    if (c == 0) v += EPSv;
                }
                Sb[i * BW + c] = v;
            }
        } else {
#pragma unroll
            for (int c = 0; c < 6; ++c)
                Sb[i * BW + c] = (c == 0) ? 1.0f : 0.0f;
        }
    }
    __syncthreads();

    // ---------------- Phase B: banded Cholesky (warp 0, 6-window) -----------
    float pld_local = 0.0f;
    if (tid < 32) {
        const int lane = tid;
        float W[6][6];
#pragma unroll
        for (int s = 0; s < 6; ++s)
#pragma unroll
            for (int c = 0; c < 6; ++c)
                W[s][c] = Sb[s * BW + c];

        float prod = 1.0f;
        float ld_skip = 0.0f;
        float lprev[6];
#pragma unroll
        for (int c = 0; c < 6; ++c) lprev[c] = -1.0f;
        bool conv = false;
        int j = 0;

        while (j < NSTEP) {
            if (conv && j <= JUMPJ - 6) {
#pragma unroll
                for (int c = 0; c < 6; ++c)
                    if (lane == c) stc[c] = lprev[c];
                __syncwarp();
                const int skip = JUMPJ - j;
                // column-wise fill: exactly what the recursion would write
                for (int idx = lane; idx < skip * BW; idx += 32) {
                    int jc = j + idx / BW;
                    int c  = idx - (idx / BW) * BW;
                    int r  = jc + c;
                    if (r < NMID)
                        Ls[r * BWP + c] = stc[c];
                }
                __syncwarp();
                ld_skip = (float)skip * __logf(lprev[0]);
                j = JUMPJ;
                conv = false;
            }
#pragma unroll
            for (int s = 0; s < 6; ++s) {
                float x = W[s][0];
                float inv = rsqrtf(x);
                float dg = x * inv;

                float l[6];
                l[0] = dg;
#pragma unroll
                for (int c = 1; c < 6; ++c)
                    l[c] = W[(s + c) % 6][c] * inv;

                if (j < JUMPJ) {
                    bool eq = true;
#pragma unroll
                    for (int c = 0; c < 6; ++c) eq = eq && (l[c] == lprev[c]);
                    if (eq && j >= 10) conv = true;
#pragma unroll
                    for (int c = 0; c < 6; ++c) lprev[c] = l[c];
                }

#pragma unroll
                for (int c = 0; c < 6; ++c)
                    if (lane == c && j + c < NMID)
                        Ls[(j + c) * BWP + c] = l[c];

#pragma unroll
                for (int r1 = 1; r1 < 6; ++r1)
#pragma unroll
                    for (int r2 = 1; r2 <= r1; ++r2)
                        W[(s + r1) % 6][r1 - r2] -= l[r1] * l[r2];

                {
                    const float* src = &Sb[(j + 6) * BW];
#pragma unroll
                    for (int c = 0; c < 6; ++c)
                        W[s][c] = src[c];
                }

                if (j < NMID) prod *= dg;
                ++j;
            }
        }
        pld_local = __logf(prod) + ld_skip;
    }
    __syncthreads();   // Ls complete, visible to all

    // ---------------- Phase C: taps from smem, pipelined apply ---------------
    float L[4][6];
    float a0[4], a1[4];
#pragma unroll
    for (int u = 0; u < 4; ++u) {
        int i = t0 + u - 1;
        bool valid = (i >= 0) && (i < NMID);
        if (valid) {
            const float4* p = reinterpret_cast<const float4*>(&Ls[i * BWP]);
            float4 f0 = p[0], f1 = p[1];
            L[u][0] = f0.x; L[u][1] = f0.y; L[u][2] = f0.z; L[u][3] = f0.w;
            L[u][4] = f1.x; L[u][5] = f1.y;
            a0[u] = A0s[i];
            a1[u] = A1s[i];
        } else {
#pragma unroll
            for (int c = 0; c < 6; ++c) L[u][c] = 0.0f;
            a0[u] = 0.0f; a1[u] = 0.0f;
        }
    }
    bool need_ep = (tg == 0) || (tg == 63);
#pragma unroll
    for (int u = 0; u < 4; ++u)
        need_ep = need_ep || (a0[u] != 0.0f) || (a1[u] != 0.0f);

    const int barid = rs + 1;

    // running pointers (avoid per-iter 64-bit multiplies)
    const float* psrc = zbase + 3 * iterstep;            // row chunk for iter it+3
    float* pdst = obase;                                 // output rows for iter it
    unsigned dst_issue = sdst_base + 3 * stage_bytes + grp_off * 4u;
    const unsigned dst_wrap = sdst_base + 4 * stage_bytes + grp_off * 4u;
    int coff = 0;                                        // consume stage float-offset

    for (int it = 0; it < niter; ++it) {
        asm volatile("cp.async.wait_group 2;\n" ::: "memory");
        asm volatile("bar.sync %0, %1;" :: "r"(barid), "n"(64) : "memory");

        if (it + 3 < niter) {
#pragma unroll
            for (int r = 0; r < RPG; ++r) {
                unsigned dst = dst_issue + r * (RSTRIDE * 4u);
                const float* src = psrc + (size_t)r * rowpitch;
                asm volatile("cp.async.cg.shared.global [%0], [%1], 16;\n" :: "r"(dst), "l"(src));
            }
        }
        asm volatile("cp.async.commit_group;\n" ::: "memory");
        psrc += iterstep;
        dst_issue += stage_bytes;
        if (dst_issue >= dst_wrap) dst_issue -= 4 * stage_bytes;

#pragma unroll
        for (int r = 0; r < RPG; ++r) {
            const float* rb = &sbuf[coff + (rs * RPG + r) * RSTRIDE];
            // trimmed 9-float window: z[t0-5 .. t0+3]
            float s5 = rb[t0 + 3];                                        // z[t0-5]
            float4 f1 = *reinterpret_cast<const float4*>(rb + t0 + 4);    // z[t0-4..t0-1]
            float4 f2 = *reinterpret_cast<const float4*>(rb + t0 + 8);    // z[t0..t0+3]
            float z0 = 0.0f, zE = 0.0f;
            if (need_ep) {
                z0 = rb[8];
                zE = rb[8 + 255];
            }

            float w[9];
            w[0] = s5;
            w[1] = f1.x; w[2] = f1.y; w[3] = f1.z; w[4] = f1.w;
            w[5] = f2.x; w[6] = f2.y; w[7] = f2.z; w[8] = f2.w;

            float v[4];
#pragma unroll
            for (int u = 0; u < 4; ++u) {
                float acc = a0[u] * z0 + a1[u] * zE;
#pragma unroll
                for (int c = 0; c < 6; ++c)
                    acc += L[u][c] * w[u - c + 5];
                v[u] = acc;
            }
            if (tg == 0)  v[0] = z0;
            if (tg == 63) v[3] = zE;

            *reinterpret_cast<float4*>(pdst + (size_t)r * rowpitch) =
                make_float4(v[0], v[1], v[2], v[3]);
        }
        pdst += iterstep;
        coff += RPS * RSTRIDE;
        if (coff == NSTAGE * RPS * RSTRIDE) coff = 0;
    }

    // ---------------- Phase D: deterministic logdet reduction ----------------
    if (chunk == 0 && tid == 0) {
        g_pld[d] = pld_local;
        __threadfence();
        int old = atomicAdd(&g_cnt, 1);
        if (old == ND - 1) {
            __threadfence();
            float s = sldj[0];
            for (int dd = 0; dd < ND; ++dd) s += g_pld[dd];   // fixed order
            out[osize - 1] = s;
            g_cnt = 0;                                        // reset for replay
        }
    }
}

extern "C" void kernel_launch(void* const* d_in, const int* in_sizes, int n_in,
                              void* d_out, int out_size) {
    const float* z = (const float*)d_in[0];
    const float* sldj = (const float*)d_in[1];
    const float* log_tau = (const float*)d_in[2];
    float* out = (float*)d_out;

    cudaFuncSetAttribute(fused_kernel, cudaFuncAttributeMaxDynamicSharedMemorySize,
                         SMEM_BYTES);
    fused_kernel<<<NBLOCKS, 256, SMEM_BYTES>>>(z, sldj, log_tau, out, out_size);
}

// round 17
// speedup vs baseline: 1.1098x; 1.1098x over previous
#include <cuda_runtime.h>
#include <cuda_bf16.h>
#include <math.h>

// z is (Kn=4, M=128, D=64, T=256)
#define Tn    256
#define NMID  254
#define ND    64
#define BW    6            // half-bandwidth 5 + diag (tau=0.5: c=6 entries ~5e-32)
#define BWP   8            // padded band stride (2x float4)
#define NPAD  264
#define NSTEP 258          // 43*6
#define JUMPJ 246          // 41*6: resume point after Toeplitz skip
#define EPSv  1e-5f

#define RSTRIDE 264        // smem row stride in floats: 8 pad + 256
#define NSTAGE  5
#define RPG     2          // rows per group per stage
#define RPS     (RPG * 4)  // 8 rows per stage

// dynamic smem layout (floats). Sb/stc/gcs OVERLAY stage 3 of the z-ring:
// stage 3 is first written by cp.async only after the recursion finishes.
#define SBUF_F   (NSTAGE * RPS * RSTRIDE)          // 10560
#define SB_OFF   (3 * RPS * RSTRIDE)               // 6336 (stage 3 start)
#define SB_F     (NPAD * BW)                       // 1584
#define STC_OFF  (SB_OFF + SB_F)                   // 7920
#define GCS_OFF  (STC_OFF + 8)                     // 7928 (stage 3 ends 8448)
#define LS_OFF   SBUF_F                            // 10560 (16B aligned)
#define LS_F     (NMID * BWP)                      // 2032
#define A0_OFF   (LS_OFF + LS_F)                   // 12592
#define A1_OFF   (A0_OFF + NMID)                   // 12846
#define SMEM_F   (A1_OFF + NMID)                   // 13100
#define SMEM_BYTES (SMEM_F * 4)                    // 52400 -> 4 blocks/SM

__device__ float g_pld[ND];
__device__ int   g_cnt = 0;

__global__ __launch_bounds__(256, 4) void fused_kernel(const float* __restrict__ z,
                                                       const float* __restrict__ sldj,
                                                       const float* __restrict__ log_tau,
                                                       float* __restrict__ out,
                                                       int osize) {
    extern __shared__ float smem[];
    float* sbuf = smem;
    float* Ls   = smem + LS_OFF;
    float* A0s  = smem + A0_OFF;
    float* A1s  = smem + A1_OFF;
    float* Sb   = smem + SB_OFF;     // [NPAD][BW] flattened (stage-3 overlay)
    float* stc  = smem + STC_OFF;
    float* gcs  = smem + GCS_OFF;

    const int d = blockIdx.x;
    const int chunk = blockIdx.y;          // 0..6: chunks of {80,80,80,80,64,64,64} rows
    const int tid = threadIdx.x;
    const int tg = tid & 63;
    const int rs = tid >> 6;               // pipeline group 0..3
    const int t0 = tg << 2;

    const int niter = (chunk < 4) ? 10 : 8;                 // iterations (2 rows each)
    const int kbase = (chunk < 4) ? chunk * 80 : 320 + (chunk - 4) * 64;

    // -------- Phase 0: fire z prefetch FIRST (independent of band build) ----
    const int km0 = kbase + rs * (niter * RPG);             // group's first row
    const float* __restrict__ zbase = z + (size_t)(km0 * ND + d) * Tn + t0;
    float* __restrict__ obase = out + (size_t)(km0 * ND + d) * Tn + t0;
    const size_t rowpitch = (size_t)ND * Tn;
    const size_t iterstep = (size_t)RPG * rowpitch;         // 2 km-rows

    unsigned sdst_base;
    {
        void* p = (void*)&sbuf[0];
        sdst_base = (unsigned)__cvta_generic_to_shared(p);
    }
    const unsigned grp_off = (rs * RPG) * RSTRIDE + 8 + t0;

#pragma unroll
    for (int p = 0; p < 3; ++p) {
#pragma unroll
        for (int r = 0; r < RPG; ++r) {
            unsigned dst = sdst_base + ((p * RPS * RSTRIDE) + grp_off + r * RSTRIDE) * 4u;
            const float* src = zbase + (size_t)p * iterstep + (size_t)r * rowpitch;
            asm volatile("cp.async.cg.shared.global [%0], [%1], 16;\n" :: "r"(dst), "l"(src));
        }
        asm volatile("cp.async.commit_group;\n" ::: "memory");
    }

    // ---------------- Phase A: band build (all 256 threads) ----------------
    const float tau = __expf(log_tau[d]);
    const float h = 1.0f / (2.0f * tau * tau);
    const float r255 = __expf(-h * 255.0f * 255.0f);
    const float idet = 1.0f / (1.0f - r255 * r255);

    if (tid < BW) gcs[tid] = __expf(-h * (float)(tid * tid));
    // zero front pads of all 40 row buffers
    for (int k = tid; k < NSTAGE * RPS * 8; k += 256)
        sbuf[(k >> 3) * RSTRIDE + (k & 7)] = 0.0f;
    // zero first 6 Ls band rows (entries c > i never written by recursion but
    // read by the unconditional tap loader; smem is not zero-initialized)
    if (tid < 6 * BWP) Ls[tid] = 0.0f;
    __syncthreads();

    for (int i = tid; i < NPAD; i += 256) {
        if (i < NMID) {
            float k0c[6], k1c[6];
#pragma unroll
            for (int c = 0; c < 6; ++c) {
                int ip = i - c;
                float x0 = (float)(ip + 1);
                float x1 = (float)(254 - ip);
                k0c[c] = __expf(-h * x0 * x0);
                k1c[c] = __expf(-h * x1 * x1);
            }
            float a0 = idet * (k0c[0] - r255 * k1c[0]);
            float a1 = idet * (k1c[0] - r255 * k0c[0]);
            A0s[i] = a0; A1s[i] = a1;
#pragma unroll
            for (int c = 0; c < 6; ++c) {
                float v = 0.0f;
                if (c <= i) {
                    v = gcs[c] - a0 * k0c[c] - a1 * k1c[c];
                    if (c == 0) v += EPSv;
                }
                Sb[i * BW + c] = v;
            }
        } else {
#pragma unroll
            for (int c = 0; c < 6; ++c)
                Sb[i * BW + c] = (c == 0) ? 1.0f : 0.0f;
        }
    }
    __syncthreads();

    // ---------------- Phase B: banded Cholesky (warp 0, 6-window) -----------
    float pld_local = 0.0f;
    if (tid < 32) {
        const int lane = tid;
        float W[6][6];
#pragma unroll
        for (int s = 0; s < 6; ++s)
#pragma unroll
            for (int c = 0; c < 6; ++c)
                W[s][c] = Sb[s * BW + c];

        float prod = 1.0f;
        float ld_skip = 0.0f;
        float lprev[6];
#pragma unroll
        for (int c = 0; c < 6; ++c) lprev[c] = -1.0f;
        bool conv = false;
        int j = 0;

        while (j < NSTEP) {
            if (conv && j <= JUMPJ - 6) {
#pragma unroll
                for (int c = 0; c < 6; ++c)
                    if (lane == c) stc[c] = lprev[c];
                __syncwarp();
                const int skip = JUMPJ - j;
                // column-wise fill: exactly what the recursion would write
                for (int idx = lane; idx < skip * BW; idx += 32) {
                    int jc = j + idx / BW;
                    int c  = idx - (idx / BW) * BW;
                    int r  = jc + c;
                    if (r < NMID)
                        Ls[r * BWP + c] = stc[c];
                }
                __syncwarp();
                ld_skip = (float)skip * __logf(lprev[0]);
                j = JUMPJ;
                conv = false;
            }
#pragma unroll
            for (int s = 0; s < 6; ++s) {
                float x = W[s][0];
                float inv = rsqrtf(x);
                float dg = x * inv;

                float l[6];
                l[0] = dg;
#pragma unroll
                for (int c = 1; c < 6; ++c)
                    l[c] = W[(s + c) % 6][c] * inv;

                if (j < JUMPJ) {
                    bool eq = true;
#pragma unroll
                    for (int c = 0; c < 6; ++c) eq = eq && (l[c] == lprev[c]);
                    if (eq && j >= 10) conv = true;
#pragma unroll
                    for (int c = 0; c < 6; ++c) lprev[c] = l[c];
                }

#pragma unroll
                for (int c = 0; c < 6; ++c)
                    if (lane == c && j + c < NMID)
                        Ls[(j + c) * BWP + c] = l[c];

#pragma unroll
                for (int r1 = 1; r1 < 6; ++r1)
#pragma unroll
                    for (int r2 = 1; r2 <= r1; ++r2)
                        W[(s + r1) % 6][r1 - r2] -= l[r1] * l[r2];

                {
                    const float* src = &Sb[(j + 6) * BW];
#pragma unroll
                    for (int c = 0; c < 6; ++c)
                        W[s][c] = src[c];
                }

                if (j < NMID) prod *= dg;
                ++j;
            }
        }
        pld_local = __logf(prod) + ld_skip;
    }
    __syncthreads();   // Ls complete; Sb dead from here on

    // re-zero stage-3 front pads (corrupted by the Sb/stc overlay)
    if (tid < RPS * 8)
        sbuf[(3 * RPS + (tid >> 3)) * RSTRIDE + (tid & 7)] = 0.0f;
    __syncthreads();

    // ---------------- Phase C: taps from smem, pipelined apply ---------------
    float L[4][6];
    float a0[4], a1[4];
#pragma unroll
    for (int u = 0; u < 4; ++u) {
        int i = t0 + u - 1;
        bool valid = (i >= 0) && (i < NMID);
        if (valid) {
            const float4* p = reinterpret_cast<const float4*>(&Ls[i * BWP]);
            float4 f0 = p[0], f1 = p[1];
            L[u][0] = f0.x; L[u][1] = f0.y; L[u][2] = f0.z; L[u][3] = f0.w;
            L[u][4] = f1.x; L[u][5] = f1.y;
            a0[u] = A0s[i];
            a1[u] = A1s[i];
        } else {
#pragma unroll
            for (int c = 0; c < 6; ++c) L[u][c] = 0.0f;
            a0[u] = 0.0f; a1[u] = 0.0f;
        }
    }
    bool need_ep = (tg == 0) || (tg == 63);
#pragma unroll
    for (int u = 0; u < 4; ++u)
        need_ep = need_ep || (a0[u] != 0.0f) || (a1[u] != 0.0f);

    // issue 4th in-flight group: stage 3 <- iter-3 rows (niter >= 8 always)
#pragma unroll
    for (int r = 0; r < RPG; ++r) {
        unsigned dst = sdst_base + ((3 * RPS * RSTRIDE) + grp_off + r * RSTRIDE) * 4u;
        const float* src = zbase + (size_t)3 * iterstep + (size_t)r * rowpitch;
        asm volatile("cp.async.cg.shared.global [%0], [%1], 16;\n" :: "r"(dst), "l"(src));
    }
    asm volatile("cp.async.commit_group;\n" ::: "memory");

    const int barid = rs + 1;
    int cstage = 0;            // consume stage
    int istage = 4;            // issue stage (for iter it+4)

    for (int it = 0; it < niter; ++it) {
        asm volatile("cp.async.wait_group 3;\n" ::: "memory");
        asm volatile("bar.sync %0, %1;" :: "r"(barid), "n"(64) : "memory");

        if (it + 4 < niter) {
#pragma unroll
            for (int r = 0; r < RPG; ++r) {
                unsigned dst = sdst_base + ((istage * RPS * RSTRIDE) + grp_off + r * RSTRIDE) * 4u;
                const float* src = zbase + (size_t)(it + 4) * iterstep + (size_t)r * rowpitch;
                asm volatile("cp.async.cg.shared.global [%0], [%1], 16;\n" :: "r"(dst), "l"(src));
            }
        }
        asm volatile("cp.async.commit_group;\n" ::: "memory");

#pragma unroll
        for (int r = 0; r < RPG; ++r) {
            const float* rb = &sbuf[(cstage * RPS + rs * RPG + r) * RSTRIDE];
            // trimmed 9-float window: z[t0-5 .. t0+3]
            float s5 = rb[t0 + 3];                                        // z[t0-5]
            float4 f1 = *reinterpret_cast<const float4*>(rb + t0 + 4);    // z[t0-4..t0-1]
            float4 f2 = *reinterpret_cast<const float4*>(rb + t0 + 8);    // z[t0..t0+3]
            float z0 = 0.0f, zE = 0.0f;
            if (need_ep) {
                z0 = rb[8];
                zE = rb[8 + 255];
            }

            float w[9];
            w[0] = s5;
            w[1] = f1.x; w[2] = f1.y; w[3] = f1.z; w[4] = f1.w;
            w[5] = f2.x; w[6] = f2.y; w[7] = f2.z; w[8] = f2.w;

            float v[4];
#pragma unroll
            for (int u = 0; u < 4; ++u) {
                float acc = a0[u] * z0 + a1[u] * zE;
#pragma unroll
                for (int c = 0; c < 6; ++c)
                    acc += L[u][c] * w[u - c + 5];
                v[u] = acc;
            }
            if (tg == 0)  v[0] = z0;
            if (tg == 63) v[3] = zE;

            *reinterpret_cast<float4*>(obase + (size_t)it * iterstep + (size_t)r * rowpitch) =
                make_float4(v[0], v[1], v[2], v[3]);
        }

        if (++cstage == NSTAGE) cstage = 0;
        if (++istage == NSTAGE) istage = 0;
    }

    // ---------------- Phase D: deterministic logdet reduction ----------------
    if (chunk == 0 && tid == 0) {
        g_pld[d] = pld_local;
        __threadfence();
        int old = atomicAdd(&g_cnt, 1);
        if (old == ND - 1) {
            __threadfence();
            float s = sldj[0];
            for (int dd = 0; dd < ND; ++dd) s += g_pld[dd];   // fixed order
            out[osize - 1] = s;
            g_cnt = 0;                                        // reset for replay
        }
    }
}

extern "C" void kernel_launch(void* const* d_in, const int* in_sizes, int n_in,
                              void* d_out, int out_size) {
    const float* z = (const float*)d_in[0];
    const float* sldj = (const float*)d_in[1];
    const float* log_tau = (const float*)d_in[2];
    float* out = (float*)d_out;

    cudaFuncSetAttribute(fused_kernel, cudaFuncAttributeMaxDynamicSharedMemorySize,
                         SMEM_BYTES);
    fused_kernel<<<dim3(ND, 7), 256, SMEM_BYTES>>>(z, sldj, log_tau, out, out_size);
}